// round 1
// baseline (speedup 1.0000x reference)
#include <cuda_runtime.h>

#define SEQ 4096
#define HID 1024
#define NLAYERS 4

// ---------------- device scratch (static, allowed) ----------------
__device__ float g_Zu[SEQ * HID];        // gate-u input term per timestep
__device__ float g_Zr[SEQ * HID];        // gate-r input term
__device__ float g_Zc[SEQ * HID];        // candidate input term (layer 0 only distinct)
__device__ float g_H[2][SEQ * HID];      // per-layer hidden history, ping-pong
__device__ float g_zero[HID];            // stays zero forever (never written)
__device__ int   g_ctr[NLAYERS];         // one spin-barrier counter per scan

__global__ void zero_ctrs_kernel() {
    if (threadIdx.x < NLAYERS) g_ctr[threadIdx.x] = 0;
}

// ---------------- fp32 SGEMM: C[4096,1024] = A[4096,1024] @ B[1024,1024]^T ----
// 128x128 tile, K-tile 8, 256 threads, 8x8 microtile.
__global__ __launch_bounds__(256) void sgemm_nt(const float* __restrict__ A,
                                                const float* __restrict__ B,
                                                float* __restrict__ C) {
    const int K = HID, N = HID;
    __shared__ float As[8][128];
    __shared__ float Bs[8][128];
    const int tid = threadIdx.x;
    const int m0 = blockIdx.y * 128;
    const int n0 = blockIdx.x * 128;
    const int tx = tid & 15;       // N dir (16)
    const int ty = tid >> 4;       // M dir (16)
    const int lrow = tid >> 1;     // 0..127
    const int kp = (tid & 1) * 4;  // 0 or 4

    const float* Ap = A + (m0 + lrow) * K + kp;
    const float* Bp = B + (n0 + lrow) * K + kp;

    float acc[8][8];
#pragma unroll
    for (int i = 0; i < 8; i++)
#pragma unroll
        for (int j = 0; j < 8; j++) acc[i][j] = 0.f;

    for (int k0 = 0; k0 < K; k0 += 8) {
        float4 av = *(const float4*)(Ap + k0);
        float4 bv = *(const float4*)(Bp + k0);
        __syncthreads();
        As[kp + 0][lrow] = av.x; As[kp + 1][lrow] = av.y;
        As[kp + 2][lrow] = av.z; As[kp + 3][lrow] = av.w;
        Bs[kp + 0][lrow] = bv.x; Bs[kp + 1][lrow] = bv.y;
        Bs[kp + 2][lrow] = bv.z; Bs[kp + 3][lrow] = bv.w;
        __syncthreads();
#pragma unroll
        for (int kk = 0; kk < 8; kk++) {
            float a[8], b[8];
#pragma unroll
            for (int i = 0; i < 8; i++) a[i] = As[kk][ty * 8 + i];
#pragma unroll
            for (int j = 0; j < 8; j++) b[j] = Bs[kk][tx * 8 + j];
#pragma unroll
            for (int i = 0; i < 8; i++)
#pragma unroll
                for (int j = 0; j < 8; j++) acc[i][j] = fmaf(a[i], b[j], acc[i][j]);
        }
    }
#pragma unroll
    for (int i = 0; i < 8; i++) {
        float* Cp = C + (m0 + ty * 8 + i) * N + n0 + tx * 8;
#pragma unroll
        for (int j = 0; j < 8; j++) Cp[j] = acc[i][j];
    }
}

// ---------------- persistent GRU layer scan ----------------
// Grid: 128 CTAs x 256 threads; warp w of CTA b owns output index j = 8b+w.
// All 3 recurrent weight rows for j live in registers (96 floats/lane).
// Per step: h(t-1) read via coalesced LDG (L2-hot), dot, warp bfly-reduce,
// gates, STG h(t), device-wide spin barrier on a monotonic counter.
__global__ __launch_bounds__(256, 1) void gru_scan(
    const float* __restrict__ Wu, const float* __restrict__ Wr, const float* __restrict__ Wc,
    const float* __restrict__ Bu, const float* __restrict__ Br, const float* __restrict__ Bc,
    const float* __restrict__ Pu, const float* __restrict__ Pr, const float* __restrict__ Pc,
    float* __restrict__ Hout, float* __restrict__ out_final, int* ctr) {
    const int warp = threadIdx.x >> 5;
    const int lane = threadIdx.x & 31;
    const int j = (blockIdx.x << 3) + warp;
    const int nc = gridDim.x;

    // weight preload: k = 128*i + 4*lane + c
    float wu[32], wr[32], wc[32];
    const float* wub = Wu + j * HID;
    const float* wrb = Wr + j * HID;
    const float* wcb = Wc + j * HID;
#pragma unroll
    for (int i = 0; i < 8; i++) {
        const int k = i * 128 + lane * 4;
        float4 a = *(const float4*)(wub + k);
        float4 b = *(const float4*)(wrb + k);
        float4 c = *(const float4*)(wcb + k);
        wu[4 * i + 0] = a.x; wu[4 * i + 1] = a.y; wu[4 * i + 2] = a.z; wu[4 * i + 3] = a.w;
        wr[4 * i + 0] = b.x; wr[4 * i + 1] = b.y; wr[4 * i + 2] = b.z; wr[4 * i + 3] = b.w;
        wc[4 * i + 0] = c.x; wc[4 * i + 1] = c.y; wc[4 * i + 2] = c.z; wc[4 * i + 3] = c.w;
    }
    const float bu = Bu[j], br = Br[j], bc = Bc[j];
    float hj = 0.f;                       // h[j] of this layer, kept in-register
    const float* hsrc = g_zero;           // h(-1) = 0
    volatile int* vctr = (volatile int*)ctr;

    for (int t = 0; t < SEQ; t++) {
        // prefetch per-step gate input terms early (latency hidden by dot)
        const float zu = __ldg(Pu + t * HID + j);
        const float zr = __ldg(Pr + t * HID + j);
        const float zc = __ldg(Pc + t * HID + j);

        float au = 0.f, ar = 0.f, ac = 0.f;
#pragma unroll
        for (int i = 0; i < 8; i++) {
            float4 h4 = *(const float4*)(hsrc + i * 128 + lane * 4);
            au = fmaf(wu[4 * i + 0], h4.x, au);
            ar = fmaf(wr[4 * i + 0], h4.x, ar);
            ac = fmaf(wc[4 * i + 0], h4.x, ac);
            au = fmaf(wu[4 * i + 1], h4.y, au);
            ar = fmaf(wr[4 * i + 1], h4.y, ar);
            ac = fmaf(wc[4 * i + 1], h4.y, ac);
            au = fmaf(wu[4 * i + 2], h4.z, au);
            ar = fmaf(wr[4 * i + 2], h4.z, ar);
            ac = fmaf(wc[4 * i + 2], h4.z, ac);
            au = fmaf(wu[4 * i + 3], h4.w, au);
            ar = fmaf(wr[4 * i + 3], h4.w, ar);
            ac = fmaf(wc[4 * i + 3], h4.w, ac);
        }
#pragma unroll
        for (int off = 16; off > 0; off >>= 1) {
            au += __shfl_xor_sync(0xffffffffu, au, off);
            ar += __shfl_xor_sync(0xffffffffu, ar, off);
            ac += __shfl_xor_sync(0xffffffffu, ac, off);
        }
        const float u = 1.f / (1.f + __expf(-(au + zu + bu)));
        const float r = 1.f / (1.f + __expf(-(ar + zr + br)));
        const float c = 1.f / (1.f + __expf(-(zc + r * ac + bc)));
        const float hn = fmaf(u, hj - c, c);   // u*h + (1-u)*c
        hj = hn;

        if (lane == 0) Hout[t * HID + j] = hn;
        __threadfence();
        __syncthreads();
        if (threadIdx.x == 0) {
            atomicAdd(ctr, 1);
            const int target = (t + 1) * nc;
            while (*vctr < target) { }
        }
        __syncthreads();
        hsrc = Hout + t * HID;   // fresh addresses each step -> no stale L1
    }
    if (lane == 0) out_final[j] = hj;
}

// ---------------- launch ----------------
extern "C" void kernel_launch(void* const* d_in, const int* in_sizes, int n_in,
                              void* d_out, int out_size) {
    const float* x   = (const float*)d_in[0];
    const float* Uu  = (const float*)d_in[1];
    const float* Ur  = (const float*)d_in[2];
    const float* U   = (const float*)d_in[3];
    const float* Wu  = (const float*)d_in[4];
    const float* Wr  = (const float*)d_in[5];
    const float* W   = (const float*)d_in[6];
    const float* Bu  = (const float*)d_in[7];
    const float* Br  = (const float*)d_in[8];
    const float* B   = (const float*)d_in[9];
    const float* Uhr = (const float*)d_in[10];
    const float* Uh  = (const float*)d_in[11];
    float* out = (float*)d_out;

    float *Zu, *Zr, *Zc, *Hb;
    int* ctr;
    cudaGetSymbolAddress((void**)&Zu, g_Zu);
    cudaGetSymbolAddress((void**)&Zr, g_Zr);
    cudaGetSymbolAddress((void**)&Zc, g_Zc);
    cudaGetSymbolAddress((void**)&Hb, g_H);
    cudaGetSymbolAddress((void**)&ctr, g_ctr);
    float* H0 = Hb;
    float* H1 = Hb + SEQ * HID;

    zero_ctrs_kernel<<<1, 32>>>();

    dim3 gg(HID / 128, SEQ / 128);  // (8, 32)

    // layer 0 input projections
    sgemm_nt<<<gg, 256>>>(x, Uu, Zu);
    sgemm_nt<<<gg, 256>>>(x, Ur, Zr);
    sgemm_nt<<<gg, 256>>>(x, U,  Zc);
    gru_scan<<<128, 256>>>(Wu, Wr, W, Bu, Br, B, Zu, Zr, Zc, H0, out, ctr);

    for (int l = 1; l < NLAYERS; l++) {
        const float* Hp = (l & 1) ? H0 : H1;
        float*       Hn = (l & 1) ? H1 : H0;
        // shared = Uh[l-1] @ h_{l-1}  (serves BOTH update gate and candidate)
        sgemm_nt<<<gg, 256>>>(Hp, Uh  + (size_t)(l - 1) * HID * HID, Zu);
        sgemm_nt<<<gg, 256>>>(Hp, Uhr + (size_t)(l - 1) * HID * HID, Zr);
        gru_scan<<<128, 256>>>(Wu + (size_t)l * HID * HID,
                               Wr + (size_t)l * HID * HID,
                               W  + (size_t)l * HID * HID,
                               Bu + l * HID, Br + l * HID, B + l * HID,
                               Zu, Zr, Zu,   // Pc aliases Pu: shared term
                               Hn, out + l * HID, ctr + l);
    }
    (void)in_sizes; (void)n_in; (void)out_size;
}